// round 1
// baseline (speedup 1.0000x reference)
#include <cuda_runtime.h>
#include <cuda_bf16.h>
#include <math.h>

// Problem: B=2, T=2048, C=768, H=12, D=64.  M = B*T = 4096 rows.
#define M_ROWS 4096
#define C_DIM  768
#define T_SEQ  2048
#define H_HEADS 12
#define D_HEAD 64
#define QKV_LD (3*C_DIM)   // 2304
#define FC_DIM (4*C_DIM)   // 3072

// ---------------- scratch (device globals: no allocation allowed) -------------
__device__ float g_xn [M_ROWS * C_DIM];    // layernorm output (reused ln1/ln2)
__device__ float g_qkv[M_ROWS * QKV_LD];   // qkv projection
__device__ float g_y  [M_ROWS * C_DIM];    // attention output (pre-proj)
__device__ float g_x2 [M_ROWS * C_DIM];    // residual after attention
__device__ float g_h  [M_ROWS * FC_DIM];   // gelu(fc)

// ---------------- LayerNorm ---------------------------------------------------
__global__ __launch_bounds__(256) void ln_kernel(const float* __restrict__ x,
                                                 const float* __restrict__ w,
                                                 float* __restrict__ out) {
    int row = blockIdx.x;
    const float* xr = x + (size_t)row * C_DIM;
    float s = 0.f, s2 = 0.f;
    for (int i = threadIdx.x; i < C_DIM; i += 256) {
        float v = xr[i];
        s += v; s2 += v * v;
    }
    #pragma unroll
    for (int o = 16; o; o >>= 1) {
        s  += __shfl_xor_sync(0xFFFFFFFFu, s,  o);
        s2 += __shfl_xor_sync(0xFFFFFFFFu, s2, o);
    }
    __shared__ float ss[8], ss2[8];
    int wid = threadIdx.x >> 5, lid = threadIdx.x & 31;
    if (lid == 0) { ss[wid] = s; ss2[wid] = s2; }
    __syncthreads();
    if (wid == 0) {
        s  = (lid < 8) ? ss[lid]  : 0.f;
        s2 = (lid < 8) ? ss2[lid] : 0.f;
        #pragma unroll
        for (int o = 4; o; o >>= 1) {
            s  += __shfl_xor_sync(0xFFFFFFFFu, s,  o);
            s2 += __shfl_xor_sync(0xFFFFFFFFu, s2, o);
        }
        if (lid == 0) { ss[0] = s; ss2[0] = s2; }
    }
    __syncthreads();
    float mean = ss[0] * (1.f / C_DIM);
    float var  = ss2[0] * (1.f / C_DIM) - mean * mean;
    float inv  = rsqrtf(var + 1e-5f);
    for (int i = threadIdx.x; i < C_DIM; i += 256)
        out[(size_t)row * C_DIM + i] = (xr[i] - mean) * inv * w[i];
}

// ---------------- SGEMM 128x128x8, 256 threads, 8x8 microtile -----------------
// MODE: 0 = C = A@B ; 1 = C = A@B + R ; 2 = C = gelu(A@B)
template<int MODE>
__global__ __launch_bounds__(256) void sgemm_kernel(
    const float* __restrict__ A, const float* __restrict__ B,
    const float* __restrict__ R, float* __restrict__ C,
    int M, int N, int K)
{
    __shared__ float As[8][132];   // padded: conflict-free transposed stores
    __shared__ float Bs[8][128];

    int tid = threadIdx.x;
    int tx = tid & 15, ty = tid >> 4;
    int m0 = blockIdx.y * 128;
    int n0 = blockIdx.x * 128;

    float acc[8][8];
    #pragma unroll
    for (int i = 0; i < 8; i++)
        #pragma unroll
        for (int j = 0; j < 8; j++) acc[i][j] = 0.f;

    int a_row = tid >> 1;           // 0..127
    int a_col = (tid & 1) * 4;      // 0 or 4
    int b_row = tid >> 5;           // 0..7
    int b_col = (tid & 31) * 4;     // 0..124

    const float* Aptr = A + (size_t)(m0 + a_row) * K + a_col;
    const float* Bptr = B + (size_t)b_row * N + n0 + b_col;

    for (int k0 = 0; k0 < K; k0 += 8) {
        float4 av = *(const float4*)(Aptr + k0);
        float4 bv = *(const float4*)(Bptr + (size_t)k0 * N);
        As[a_col + 0][a_row] = av.x;
        As[a_col + 1][a_row] = av.y;
        As[a_col + 2][a_row] = av.z;
        As[a_col + 3][a_row] = av.w;
        *(float4*)&Bs[b_row][b_col] = bv;
        __syncthreads();
        #pragma unroll
        for (int k = 0; k < 8; k++) {
            float a[8], b[8];
            *(float4*)&a[0] = *(const float4*)&As[k][ty * 4];
            *(float4*)&a[4] = *(const float4*)&As[k][64 + ty * 4];
            *(float4*)&b[0] = *(const float4*)&Bs[k][tx * 4];
            *(float4*)&b[4] = *(const float4*)&Bs[k][64 + tx * 4];
            #pragma unroll
            for (int i = 0; i < 8; i++)
                #pragma unroll
                for (int j = 0; j < 8; j++)
                    acc[i][j] += a[i] * b[j];
        }
        __syncthreads();
    }

    #pragma unroll
    for (int iq = 0; iq < 2; iq++) {
        #pragma unroll
        for (int i = 0; i < 4; i++) {
            int r = m0 + iq * 64 + ty * 4 + i;
            #pragma unroll
            for (int jq = 0; jq < 2; jq++) {
                int c = n0 + jq * 64 + tx * 4;
                float v0 = acc[iq * 4 + i][jq * 4 + 0];
                float v1 = acc[iq * 4 + i][jq * 4 + 1];
                float v2 = acc[iq * 4 + i][jq * 4 + 2];
                float v3 = acc[iq * 4 + i][jq * 4 + 3];
                if (MODE == 1) {
                    float4 rv = *(const float4*)(R + (size_t)r * N + c);
                    v0 += rv.x; v1 += rv.y; v2 += rv.z; v3 += rv.w;
                }
                if (MODE == 2) {
                    v0 = 0.5f * v0 * (1.0f + erff(v0 * 0.70710678118654752f));
                    v1 = 0.5f * v1 * (1.0f + erff(v1 * 0.70710678118654752f));
                    v2 = 0.5f * v2 * (1.0f + erff(v2 * 0.70710678118654752f));
                    v3 = 0.5f * v3 * (1.0f + erff(v3 * 0.70710678118654752f));
                }
                float4 ov = make_float4(v0, v1, v2, v3);
                *(float4*)(C + (size_t)r * N + c) = ov;
            }
        }
    }
}

// ---------------- Attention: exp(-sq_l2/(2 sqrt(D))), causal, unnormalized ----
// Per block: one (b, h, 64-query tile). Loops over key tiles kt <= qt.
#define AT_STRIDE 68     // 64 + 4 pad, keeps float4 alignment & breaks bank conflicts

__global__ __launch_bounds__(256) void attn_kernel(const float* __restrict__ qkv,
                                                   float* __restrict__ y) {
    int qt = blockIdx.x;    // 0..31
    int h  = blockIdx.y;    // 0..11
    int b  = blockIdx.z;    // 0..1

    extern __shared__ float sm[];
    float* Qs = sm;                          // 64 x 68
    float* Ks = Qs + 64 * AT_STRIDE;
    float* Vs = Ks + 64 * AT_STRIDE;
    float* Ss = Vs + 64 * AT_STRIDE;
    float* q2 = Ss + 64 * AT_STRIDE;         // 64
    float* k2 = q2 + 64;                     // 64

    int tid = threadIdx.x;
    int tx = tid & 15, ty = tid >> 4;
    const float scale = -0.0625f;            // -1/(2*sqrt(64))

    // load Q tile (coalesced float4)
    const float* qbase = qkv + ((size_t)(b * T_SEQ + qt * 64)) * QKV_LD + h * 64;
    for (int i = tid; i < 64 * 16; i += 256) {
        int row = i >> 4;
        int c4  = (i & 15) * 4;
        *(float4*)(Qs + row * AT_STRIDE + c4) =
            *(const float4*)(qbase + (size_t)row * QKV_LD + c4);
    }
    __syncthreads();
    if (tid < 64) {
        float s = 0.f;
        #pragma unroll 8
        for (int d = 0; d < 64; d++) { float v = Qs[tid * AT_STRIDE + d]; s += v * v; }
        q2[tid] = s;
    }

    float acc[4][4];
    #pragma unroll
    for (int i = 0; i < 4; i++)
        #pragma unroll
        for (int j = 0; j < 4; j++) acc[i][j] = 0.f;

    for (int kt = 0; kt <= qt; kt++) {
        __syncthreads();   // prev iter's smem reads done; q2 visible on iter 0
        const float* kbase = qkv + ((size_t)(b * T_SEQ + kt * 64)) * QKV_LD + C_DIM + h * 64;
        const float* vbase = kbase + C_DIM;
        for (int i = tid; i < 64 * 16; i += 256) {
            int row = i >> 4;
            int c4  = (i & 15) * 4;
            *(float4*)(Ks + row * AT_STRIDE + c4) =
                *(const float4*)(kbase + (size_t)row * QKV_LD + c4);
            *(float4*)(Vs + row * AT_STRIDE + c4) =
                *(const float4*)(vbase + (size_t)row * QKV_LD + c4);
        }
        __syncthreads();
        if (tid < 64) {
            float s = 0.f;
            #pragma unroll 8
            for (int d = 0; d < 64; d++) { float v = Ks[tid * AT_STRIDE + d]; s += v * v; }
            k2[tid] = s;
        }
        __syncthreads();

        // S = Q @ K^T  (4x4 per thread)
        float s_[4][4];
        #pragma unroll
        for (int i = 0; i < 4; i++)
            #pragma unroll
            for (int j = 0; j < 4; j++) s_[i][j] = 0.f;

        #pragma unroll 4
        for (int d4 = 0; d4 < 64; d4 += 4) {
            float4 qv[4], kv[4];
            #pragma unroll
            for (int i = 0; i < 4; i++)
                qv[i] = *(const float4*)(Qs + (ty * 4 + i) * AT_STRIDE + d4);
            #pragma unroll
            for (int j = 0; j < 4; j++)
                kv[j] = *(const float4*)(Ks + (tx * 4 + j) * AT_STRIDE + d4);
            #pragma unroll
            for (int i = 0; i < 4; i++)
                #pragma unroll
                for (int j = 0; j < 4; j++)
                    s_[i][j] += qv[i].x * kv[j].x + qv[i].y * kv[j].y
                              + qv[i].z * kv[j].z + qv[i].w * kv[j].w;
        }

        // scores = exp(scale*(q2 + k2 - 2*qk)), causal mask, write to Ss
        #pragma unroll
        for (int i = 0; i < 4; i++) {
            int r = ty * 4 + i;
            int qq = qt * 64 + r;
            float q2v = q2[r];
            float4 ov;
            float* o = &ov.x;
            #pragma unroll
            for (int j = 0; j < 4; j++) {
                int cc = tx * 4 + j;
                int kk = kt * 64 + cc;
                float val = __expf(scale * (q2v + k2[cc] - 2.f * s_[i][j]));
                o[j] = (kk <= qq) ? val : 0.f;
            }
            *(float4*)(Ss + r * AT_STRIDE + tx * 4) = ov;
        }
        __syncthreads();

        // Y += Ss @ Vs   (rows = queries, cols = head dim)
        #pragma unroll 4
        for (int c4 = 0; c4 < 64; c4 += 4) {
            float4 sv[4], vv[4];
            #pragma unroll
            for (int i = 0; i < 4; i++)
                sv[i] = *(const float4*)(Ss + (ty * 4 + i) * AT_STRIDE + c4);
            #pragma unroll
            for (int cc = 0; cc < 4; cc++)
                vv[cc] = *(const float4*)(Vs + (c4 + cc) * AT_STRIDE + tx * 4);
            #pragma unroll
            for (int i = 0; i < 4; i++) {
                acc[i][0] += sv[i].x * vv[0].x + sv[i].y * vv[1].x + sv[i].z * vv[2].x + sv[i].w * vv[3].x;
                acc[i][1] += sv[i].x * vv[0].y + sv[i].y * vv[1].y + sv[i].z * vv[2].y + sv[i].w * vv[3].y;
                acc[i][2] += sv[i].x * vv[0].z + sv[i].y * vv[1].z + sv[i].z * vv[2].z + sv[i].w * vv[3].z;
                acc[i][3] += sv[i].x * vv[0].w + sv[i].y * vv[1].w + sv[i].z * vv[2].w + sv[i].w * vv[3].w;
            }
        }
    }

    float* ybase = y + ((size_t)(b * T_SEQ + qt * 64)) * C_DIM + h * 64;
    #pragma unroll
    for (int i = 0; i < 4; i++) {
        float4 ov = make_float4(acc[i][0], acc[i][1], acc[i][2], acc[i][3]);
        *(float4*)(ybase + (size_t)(ty * 4 + i) * C_DIM + tx * 4) = ov;
    }
}

// ---------------- launch ------------------------------------------------------
extern "C" void kernel_launch(void* const* d_in, const int* in_sizes, int n_in,
                              void* d_out, int out_size) {
    const float* x           = (const float*)d_in[0];
    const float* w_ln1       = (const float*)d_in[1];
    const float* w_attn      = (const float*)d_in[2];
    const float* w_attn_proj = (const float*)d_in[3];
    const float* w_ln2       = (const float*)d_in[4];
    const float* w_fc        = (const float*)d_in[5];
    const float* w_mlp_proj  = (const float*)d_in[6];
    float* out = (float*)d_out;

    float *xn, *qkv, *y, *x2, *hbuf;
    cudaGetSymbolAddress((void**)&xn,   g_xn);
    cudaGetSymbolAddress((void**)&qkv,  g_qkv);
    cudaGetSymbolAddress((void**)&y,    g_y);
    cudaGetSymbolAddress((void**)&x2,   g_x2);
    cudaGetSymbolAddress((void**)&hbuf, g_h);

    const int ATTN_SMEM = (4 * 64 * AT_STRIDE + 128) * sizeof(float);  // 70144
    cudaFuncSetAttribute(attn_kernel, cudaFuncAttributeMaxDynamicSharedMemorySize, ATTN_SMEM);

    // 1. ln1(x) -> xn
    ln_kernel<<<M_ROWS, 256>>>(x, w_ln1, xn);
    // 2. qkv = xn @ w_attn
    sgemm_kernel<0><<<dim3(QKV_LD / 128, M_ROWS / 128), 256>>>(xn, w_attn, nullptr, qkv,
                                                               M_ROWS, QKV_LD, C_DIM);
    // 3. attention -> y
    attn_kernel<<<dim3(T_SEQ / 64, H_HEADS, 2), 256, ATTN_SMEM>>>(qkv, y);
    // 4. x2 = y @ w_attn_proj + x
    sgemm_kernel<1><<<dim3(C_DIM / 128, M_ROWS / 128), 256>>>(y, w_attn_proj, x, x2,
                                                              M_ROWS, C_DIM, C_DIM);
    // 5. ln2(x2) -> xn
    ln_kernel<<<M_ROWS, 256>>>(x2, w_ln2, xn);
    // 6. h = gelu(xn @ w_fc)
    sgemm_kernel<2><<<dim3(FC_DIM / 128, M_ROWS / 128), 256>>>(xn, w_fc, nullptr, hbuf,
                                                               M_ROWS, FC_DIM, C_DIM);
    // 7. out = h @ w_mlp_proj + x2
    sgemm_kernel<1><<<dim3(C_DIM / 128, M_ROWS / 128), 256>>>(hbuf, w_mlp_proj, x2, out,
                                                              M_ROWS, C_DIM, FC_DIM);
}

// round 3
// speedup vs baseline: 1.6905x; 1.6905x over previous
#include <cuda_runtime.h>
#include <cuda_bf16.h>
#include <math.h>
#include <cstdint>

// Problem: B=2, T=2048, C=768, H=12, D=64.  M = B*T = 4096 rows.
#define M_ROWS 4096
#define C_DIM  768
#define T_SEQ  2048
#define H_HEADS 12
#define D_HEAD 64
#define QKV_LD (3*C_DIM)   // 2304
#define FC_DIM (4*C_DIM)   // 3072

// ---------------- scratch (device globals: no allocation allowed) -------------
__device__ float g_xn [M_ROWS * C_DIM];
__device__ float g_qkv[M_ROWS * QKV_LD];
__device__ float g_y  [M_ROWS * C_DIM];
__device__ float g_x2 [M_ROWS * C_DIM];
__device__ float g_h  [M_ROWS * FC_DIM];
// transposed (K-major, tf32-rounded) weights
__device__ float g_wattnT[QKV_LD * C_DIM];
__device__ float g_wprojT[C_DIM * C_DIM];
__device__ float g_wfcT  [FC_DIM * C_DIM];
__device__ float g_wmlpT [C_DIM * FC_DIM];

// ======================= helpers ==============================================
__device__ __forceinline__ uint32_t smem_u32(const void* p) {
    uint32_t a;
    asm("{ .reg .u64 t; cvta.to.shared.u64 t, %1; cvt.u32.u64 %0, t; }" : "=r"(a) : "l"(p));
    return a;
}
__device__ __forceinline__ void cp_async16(uint32_t s, const void* g) {
    asm volatile("cp.async.cg.shared.global [%0], [%1], 16;" :: "r"(s), "l"(g));
}
#define CP_COMMIT() asm volatile("cp.async.commit_group;" ::: "memory")
#define CP_WAIT(n)  asm volatile("cp.async.wait_group %0;" :: "n"(n) : "memory")

__device__ __forceinline__ uint32_t to_tf32(float v) {
    uint32_t r;
    asm("cvt.rna.tf32.f32 %0, %1;" : "=r"(r) : "f"(v));
    return r;
}
// D(16x8) += A(16x8, row) * B(8x8, col) with tf32 inputs, fp32 accum
__device__ __forceinline__ void mma_tf32(float* d, const uint32_t* a, const uint32_t* b) {
    asm volatile(
        "mma.sync.aligned.m16n8k8.row.col.f32.tf32.tf32.f32 "
        "{%0,%1,%2,%3}, {%4,%5,%6,%7}, {%8,%9}, {%0,%1,%2,%3};"
        : "+f"(d[0]), "+f"(d[1]), "+f"(d[2]), "+f"(d[3])
        : "r"(a[0]), "r"(a[1]), "r"(a[2]), "r"(a[3]), "r"(b[0]), "r"(b[1]));
}

// ---------------- LayerNorm ---------------------------------------------------
__global__ __launch_bounds__(256) void ln_kernel(const float* __restrict__ x,
                                                 const float* __restrict__ w,
                                                 float* __restrict__ out) {
    int row = blockIdx.x;
    const float* xr = x + (size_t)row * C_DIM;
    float s = 0.f, s2 = 0.f;
    for (int i = threadIdx.x; i < C_DIM; i += 256) {
        float v = xr[i];
        s += v; s2 += v * v;
    }
    #pragma unroll
    for (int o = 16; o; o >>= 1) {
        s  += __shfl_xor_sync(0xFFFFFFFFu, s,  o);
        s2 += __shfl_xor_sync(0xFFFFFFFFu, s2, o);
    }
    __shared__ float ss[8], ss2[8];
    int wid = threadIdx.x >> 5, lid = threadIdx.x & 31;
    if (lid == 0) { ss[wid] = s; ss2[wid] = s2; }
    __syncthreads();
    if (wid == 0) {
        s  = (lid < 8) ? ss[lid]  : 0.f;
        s2 = (lid < 8) ? ss2[lid] : 0.f;
        #pragma unroll
        for (int o = 4; o; o >>= 1) {
            s  += __shfl_xor_sync(0xFFFFFFFFu, s,  o);
            s2 += __shfl_xor_sync(0xFFFFFFFFu, s2, o);
        }
        if (lid == 0) { ss[0] = s; ss2[0] = s2; }
    }
    __syncthreads();
    float mean = ss[0] * (1.f / C_DIM);
    float var  = ss2[0] * (1.f / C_DIM) - mean * mean;
    float inv  = rsqrtf(var + 1e-5f);
    for (int i = threadIdx.x; i < C_DIM; i += 256)
        out[(size_t)row * C_DIM + i] = (xr[i] - mean) * inv * w[i];
}

// ---------------- Weight transpose + tf32 rounding ----------------------------
// in: [rows][cols] -> out: [cols][rows] (K-major), tf32-rounded
__global__ __launch_bounds__(256) void transpose_tf32_kernel(const float* __restrict__ in,
                                                             float* __restrict__ out,
                                                             int rows, int cols) {
    __shared__ float tile[32][33];
    int bx = blockIdx.x * 32;
    int by = blockIdx.y * 32;
    int x = bx + threadIdx.x;
    #pragma unroll
    for (int j = 0; j < 32; j += 8)
        tile[threadIdx.y + j][threadIdx.x] = in[(size_t)(by + threadIdx.y + j) * cols + x];
    __syncthreads();
    int ox = by + threadIdx.x;
    #pragma unroll
    for (int j = 0; j < 32; j += 8) {
        float v = tile[threadIdx.x][threadIdx.y + j];
        out[(size_t)(bx + threadIdx.y + j) * rows + ox] = __uint_as_float(to_tf32(v));
    }
}

// ---------------- mma.sync TF32 GEMM, 128x128 tile, K-chunks of 32 ------------
// A: [M][K] fp32 (cvt on smem store).  BT: [N][K] pre-rounded tf32.
// MODE 0: C = A@B ; MODE 1: C = A@B + R ; MODE 2: C = gelu(A@B)
#define GSTR 36
#define GBUF (128 * GSTR)                  // floats per buffer
#define GEMM_SMEM_BYTES (4 * GBUF * 4)     // A x2 + B x2 = 73728

template<int MODE>
__global__ __launch_bounds__(256) void mma_gemm_kernel(
    const float* __restrict__ A, const float* __restrict__ BT,
    const float* __restrict__ R, float* __restrict__ C,
    int M, int N, int K)
{
    extern __shared__ float smf[];
    float* As = smf;              // [2][128][GSTR]
    float* Bs = smf + 2 * GBUF;   // [2][128][GSTR]
    uint32_t Bs_u = smem_u32(Bs);

    int tid  = threadIdx.x;
    int wid  = tid >> 5, lane = tid & 31;
    int wm   = wid & 1;          // 0..1 : 64-row slab
    int wn   = wid >> 1;         // 0..3 : 32-col slab
    int g    = lane >> 2, t4 = lane & 3;
    int m0 = blockIdx.y * 128, n0 = blockIdx.x * 128;

    int lrow = tid >> 3;         // 0..31 within a 32-row group
    int lc4  = (tid & 7) * 4;    // 0..28

    float acc[4][4][4];
    #pragma unroll
    for (int i = 0; i < 4; i++)
        #pragma unroll
        for (int j = 0; j < 4; j++)
            #pragma unroll
            for (int q = 0; q < 4; q++) acc[i][j][q] = 0.f;

    const int nch = K >> 5;
    float4 aprf[4];

    // ---- prologue: chunk 0 ----
    #pragma unroll
    for (int t = 0; t < 4; t++) {
        int row = t * 32 + lrow;
        aprf[t] = *(const float4*)(A + (size_t)(m0 + row) * K + lc4);
        cp_async16(Bs_u + (uint32_t)((row * GSTR + lc4) * 4),
                   BT + (size_t)(n0 + row) * K + lc4);
    }
    CP_COMMIT();
    #pragma unroll
    for (int t = 0; t < 4; t++) {
        int row = t * 32 + lrow;
        uint32_t* dst = (uint32_t*)(As + row * GSTR + lc4);
        dst[0] = to_tf32(aprf[t].x); dst[1] = to_tf32(aprf[t].y);
        dst[2] = to_tf32(aprf[t].z); dst[3] = to_tf32(aprf[t].w);
    }

    int buf = 0;
    for (int ic = 0; ic < nch; ic++) {
        bool more = (ic + 1) < nch;
        if (more) {
            int k0 = (ic + 1) * 32;
            int nb = buf ^ 1;
            #pragma unroll
            for (int t = 0; t < 4; t++) {
                int row = t * 32 + lrow;
                aprf[t] = *(const float4*)(A + (size_t)(m0 + row) * K + k0 + lc4);
                cp_async16(Bs_u + (uint32_t)((nb * GBUF + row * GSTR + lc4) * 4),
                           BT + (size_t)(n0 + row) * K + k0 + lc4);
            }
            CP_COMMIT();
            CP_WAIT(1);
        } else {
            CP_WAIT(0);
        }
        __syncthreads();

        const uint32_t* Au = (const uint32_t*)(As + buf * GBUF);
        const uint32_t* Bu = (const uint32_t*)(Bs + buf * GBUF);
        #pragma unroll
        for (int ks = 0; ks < 4; ks++) {
            uint32_t a[4][4], b[4][2];
            #pragma unroll
            for (int mt = 0; mt < 4; mt++) {
                int r = wm * 64 + mt * 16 + g;
                a[mt][0] = Au[(r)     * GSTR + ks * 8 + t4];
                a[mt][1] = Au[(r + 8) * GSTR + ks * 8 + t4];
                a[mt][2] = Au[(r)     * GSTR + ks * 8 + t4 + 4];
                a[mt][3] = Au[(r + 8) * GSTR + ks * 8 + t4 + 4];
            }
            #pragma unroll
            for (int nt = 0; nt < 4; nt++) {
                int nr = wn * 32 + nt * 8 + g;
                b[nt][0] = Bu[nr * GSTR + ks * 8 + t4];
                b[nt][1] = Bu[nr * GSTR + ks * 8 + t4 + 4];
            }
            #pragma unroll
            for (int mt = 0; mt < 4; mt++)
                #pragma unroll
                for (int nt = 0; nt < 4; nt++)
                    mma_tf32(acc[mt][nt], a[mt], b[nt]);
        }

        if (more) {
            int nb = buf ^ 1;
            #pragma unroll
            for (int t = 0; t < 4; t++) {
                int row = t * 32 + lrow;
                uint32_t* dst = (uint32_t*)(As + nb * GBUF + row * GSTR + lc4);
                dst[0] = to_tf32(aprf[t].x); dst[1] = to_tf32(aprf[t].y);
                dst[2] = to_tf32(aprf[t].z); dst[3] = to_tf32(aprf[t].w);
            }
        }
        __syncthreads();
        buf ^= 1;
    }

    // ---- epilogue ----
    #pragma unroll
    for (int mt = 0; mt < 4; mt++) {
        int r0 = m0 + wm * 64 + mt * 16 + g;
        #pragma unroll
        for (int nt = 0; nt < 4; nt++) {
            int c = n0 + wn * 32 + nt * 8 + 2 * t4;
            #pragma unroll
            for (int half = 0; half < 2; half++) {
                int r = r0 + half * 8;
                float v0 = acc[mt][nt][half * 2 + 0];
                float v1 = acc[mt][nt][half * 2 + 1];
                if (MODE == 1) {
                    float2 rv = *(const float2*)(R + (size_t)r * N + c);
                    v0 += rv.x; v1 += rv.y;
                }
                if (MODE == 2) {
                    v0 = 0.5f * v0 * (1.0f + erff(v0 * 0.70710678118654752f));
                    v1 = 0.5f * v1 * (1.0f + erff(v1 * 0.70710678118654752f));
                }
                *(float2*)(C + (size_t)r * N + c) = make_float2(v0, v1);
            }
        }
    }
}

// ---------------- Attention: exp(-sq_l2/(2 sqrt(D))), causal, unnormalized ----
#define AT_STRIDE 68

__global__ __launch_bounds__(256) void attn_kernel(const float* __restrict__ qkv,
                                                   float* __restrict__ y) {
    int qt = blockIdx.x;
    int h  = blockIdx.y;
    int b  = blockIdx.z;

    extern __shared__ float sm[];
    float* Qs = sm;
    float* Ks = Qs + 64 * AT_STRIDE;
    float* Vs = Ks + 64 * AT_STRIDE;
    float* Ss = Vs + 64 * AT_STRIDE;
    float* q2 = Ss + 64 * AT_STRIDE;
    float* k2 = q2 + 64;

    int tid = threadIdx.x;
    int tx = tid & 15, ty = tid >> 4;
    const float scale = -0.0625f;

    const float* qbase = qkv + ((size_t)(b * T_SEQ + qt * 64)) * QKV_LD + h * 64;
    for (int i = tid; i < 64 * 16; i += 256) {
        int row = i >> 4;
        int c4  = (i & 15) * 4;
        *(float4*)(Qs + row * AT_STRIDE + c4) =
            *(const float4*)(qbase + (size_t)row * QKV_LD + c4);
    }
    __syncthreads();
    if (tid < 64) {
        float s = 0.f;
        #pragma unroll 8
        for (int d = 0; d < 64; d++) { float v = Qs[tid * AT_STRIDE + d]; s += v * v; }
        q2[tid] = s;
    }

    float acc[4][4];
    #pragma unroll
    for (int i = 0; i < 4; i++)
        #pragma unroll
        for (int j = 0; j < 4; j++) acc[i][j] = 0.f;

    for (int kt = 0; kt <= qt; kt++) {
        __syncthreads();
        const float* kbase = qkv + ((size_t)(b * T_SEQ + kt * 64)) * QKV_LD + C_DIM + h * 64;
        const float* vbase = kbase + C_DIM;
        for (int i = tid; i < 64 * 16; i += 256) {
            int row = i >> 4;
            int c4  = (i & 15) * 4;
            *(float4*)(Ks + row * AT_STRIDE + c4) =
                *(const float4*)(kbase + (size_t)row * QKV_LD + c4);
            *(float4*)(Vs + row * AT_STRIDE + c4) =
                *(const float4*)(vbase + (size_t)row * QKV_LD + c4);
        }
        __syncthreads();
        if (tid < 64) {
            float s = 0.f;
            #pragma unroll 8
            for (int d = 0; d < 64; d++) { float v = Ks[tid * AT_STRIDE + d]; s += v * v; }
            k2[tid] = s;
        }
        __syncthreads();

        float s_[4][4];
        #pragma unroll
        for (int i = 0; i < 4; i++)
            #pragma unroll
            for (int j = 0; j < 4; j++) s_[i][j] = 0.f;

        #pragma unroll 4
        for (int d4 = 0; d4 < 64; d4 += 4) {
            float4 qv[4], kv[4];
            #pragma unroll
            for (int i = 0; i < 4; i++)
                qv[i] = *(const float4*)(Qs + (ty * 4 + i) * AT_STRIDE + d4);
            #pragma unroll
            for (int j = 0; j < 4; j++)
                kv[j] = *(const float4*)(Ks + (tx * 4 + j) * AT_STRIDE + d4);
            #pragma unroll
            for (int i = 0; i < 4; i++)
                #pragma unroll
                for (int j = 0; j < 4; j++)
                    s_[i][j] += qv[i].x * kv[j].x + qv[i].y * kv[j].y
                              + qv[i].z * kv[j].z + qv[i].w * kv[j].w;
        }

        #pragma unroll
        for (int i = 0; i < 4; i++) {
            int r = ty * 4 + i;
            int qq = qt * 64 + r;
            float q2v = q2[r];
            float4 ov;
            float* o = &ov.x;
            #pragma unroll
            for (int j = 0; j < 4; j++) {
                int cc = tx * 4 + j;
                int kk = kt * 64 + cc;
                float val = __expf(scale * (q2v + k2[cc] - 2.f * s_[i][j]));
                o[j] = (kk <= qq) ? val : 0.f;
            }
            *(float4*)(Ss + r * AT_STRIDE + tx * 4) = ov;
        }
        __syncthreads();

        #pragma unroll 4
        for (int c4 = 0; c4 < 64; c4 += 4) {
            float4 sv[4], vv[4];
            #pragma unroll
            for (int i = 0; i < 4; i++)
                sv[i] = *(const float4*)(Ss + (ty * 4 + i) * AT_STRIDE + c4);
            #pragma unroll
            for (int cc = 0; cc < 4; cc++)
                vv[cc] = *(const float4*)(Vs + (c4 + cc) * AT_STRIDE + tx * 4);
            #pragma unroll
            for (int i = 0; i < 4; i++) {
                acc[i][0] += sv[i].x * vv[0].x + sv[i].y * vv[1].x + sv[i].z * vv[2].x + sv[i].w * vv[3].x;
                acc[i][1] += sv[i].x * vv[0].y + sv[i].y * vv[1].y + sv[i].z * vv[2].y + sv[i].w * vv[3].y;
                acc[i][2] += sv[i].x * vv[0].z + sv[i].y * vv[1].z + sv[i].z * vv[2].z + sv[i].w * vv[3].z;
                acc[i][3] += sv[i].x * vv[0].w + sv[i].y * vv[1].w + sv[i].z * vv[2].w + sv[i].w * vv[3].w;
            }
        }
    }

    float* ybase = y + ((size_t)(b * T_SEQ + qt * 64)) * C_DIM + h * 64;
    #pragma unroll
    for (int i = 0; i < 4; i++) {
        float4 ov = make_float4(acc[i][0], acc[i][1], acc[i][2], acc[i][3]);
        *(float4*)(ybase + (size_t)(ty * 4 + i) * C_DIM + tx * 4) = ov;
    }
}

// ---------------- launch ------------------------------------------------------
extern "C" void kernel_launch(void* const* d_in, const int* in_sizes, int n_in,
                              void* d_out, int out_size) {
    const float* x           = (const float*)d_in[0];
    const float* w_ln1       = (const float*)d_in[1];
    const float* w_attn      = (const float*)d_in[2];
    const float* w_attn_proj = (const float*)d_in[3];
    const float* w_ln2       = (const float*)d_in[4];
    const float* w_fc        = (const float*)d_in[5];
    const float* w_mlp_proj  = (const float*)d_in[6];
    float* out = (float*)d_out;

    float *xn, *qkv, *y, *x2, *hbuf, *wattnT, *wprojT, *wfcT, *wmlpT;
    cudaGetSymbolAddress((void**)&xn,     g_xn);
    cudaGetSymbolAddress((void**)&qkv,    g_qkv);
    cudaGetSymbolAddress((void**)&y,      g_y);
    cudaGetSymbolAddress((void**)&x2,     g_x2);
    cudaGetSymbolAddress((void**)&hbuf,   g_h);
    cudaGetSymbolAddress((void**)&wattnT, g_wattnT);
    cudaGetSymbolAddress((void**)&wprojT, g_wprojT);
    cudaGetSymbolAddress((void**)&wfcT,   g_wfcT);
    cudaGetSymbolAddress((void**)&wmlpT,  g_wmlpT);

    const int ATTN_SMEM = (4 * 64 * AT_STRIDE + 128) * sizeof(float);
    cudaFuncSetAttribute(attn_kernel, cudaFuncAttributeMaxDynamicSharedMemorySize, ATTN_SMEM);
    cudaFuncSetAttribute(mma_gemm_kernel<0>, cudaFuncAttributeMaxDynamicSharedMemorySize, GEMM_SMEM_BYTES);
    cudaFuncSetAttribute(mma_gemm_kernel<1>, cudaFuncAttributeMaxDynamicSharedMemorySize, GEMM_SMEM_BYTES);
    cudaFuncSetAttribute(mma_gemm_kernel<2>, cudaFuncAttributeMaxDynamicSharedMemorySize, GEMM_SMEM_BYTES);

    dim3 tb(32, 8);
    transpose_tf32_kernel<<<dim3(QKV_LD / 32, C_DIM / 32), tb>>>(w_attn,      wattnT, C_DIM,  QKV_LD);
    transpose_tf32_kernel<<<dim3(C_DIM / 32,  C_DIM / 32), tb>>>(w_attn_proj, wprojT, C_DIM,  C_DIM);
    transpose_tf32_kernel<<<dim3(FC_DIM / 32, C_DIM / 32), tb>>>(w_fc,        wfcT,   C_DIM,  FC_DIM);
    transpose_tf32_kernel<<<dim3(C_DIM / 32,  FC_DIM / 32), tb>>>(w_mlp_proj, wmlpT,  FC_DIM, C_DIM);

    // 1. ln1(x) -> xn
    ln_kernel<<<M_ROWS, 256>>>(x, w_ln1, xn);
    // 2. qkv = xn @ w_attn
    mma_gemm_kernel<0><<<dim3(QKV_LD / 128, M_ROWS / 128), 256, GEMM_SMEM_BYTES>>>(
        xn, wattnT, nullptr, qkv, M_ROWS, QKV_LD, C_DIM);
    // 3. attention -> y
    attn_kernel<<<dim3(T_SEQ / 64, H_HEADS, 2), 256, ATTN_SMEM>>>(qkv, y);
    // 4. x2 = y @ w_attn_proj + x
    mma_gemm_kernel<1><<<dim3(C_DIM / 128, M_ROWS / 128), 256, GEMM_SMEM_BYTES>>>(
        y, wprojT, x, x2, M_ROWS, C_DIM, C_DIM);
    // 5. ln2(x2) -> xn
    ln_kernel<<<M_ROWS, 256>>>(x2, w_ln2, xn);
    // 6. h = gelu(xn @ w_fc)
    mma_gemm_kernel<2><<<dim3(FC_DIM / 128, M_ROWS / 128), 256, GEMM_SMEM_BYTES>>>(
        xn, wfcT, nullptr, hbuf, M_ROWS, FC_DIM, C_DIM);
    // 7. out = h @ w_mlp_proj + x2
    mma_gemm_kernel<1><<<dim3(C_DIM / 128, M_ROWS / 128), 256, GEMM_SMEM_BYTES>>>(
        hbuf, wmlpT, x2, out, M_ROWS, C_DIM, FC_DIM);
}